// round 6
// baseline (speedup 1.0000x reference)
#include <cuda_runtime.h>

#define N_NODES    262144
#define N_EDGES    4194304
#define NUM_GRAPHS 1024

typedef unsigned long long u64;

// ---------------- scratch (device globals; no allocations allowed) ----------
__device__ ulonglong2 g_pd[N_NODES * 4];   // per-node dst-part of layer1 (incl b1): 16 f32
__device__ ulonglong2 g_ps[N_NODES * 4];   // per-node src-part of layer1: 16 f32
__device__ float4     g_pos4[N_NODES];     // padded pos
__device__ float4     g_agg[N_NODES * 4];  // agg: (N_NODES, 16) f32
__device__ float      g_cnt[N_NODES];      // cnt
__device__ float4     g_pooled[NUM_GRAPHS * 8]; // pooled: (NUM_GRAPHS, 2, 16)

// ---------------- packed f32x2 helpers (Blackwell FFMA2 path) ----------------
__device__ __forceinline__ u64 pack2(float lo, float hi) {
    u64 r; asm("mov.b64 %0, {%1,%2};" : "=l"(r) : "f"(lo), "f"(hi)); return r;
}
__device__ __forceinline__ void unpack2(u64 v, float& lo, float& hi) {
    asm("mov.b64 {%0,%1}, %2;" : "=f"(lo), "=f"(hi) : "l"(v));
}
__device__ __forceinline__ u64 fma2(u64 a, u64 b, u64 c) {
    u64 d; asm("fma.rn.f32x2 %0, %1, %2, %3;" : "=l"(d) : "l"(a), "l"(b), "l"(c)); return d;
}
__device__ __forceinline__ u64 add2(u64 a, u64 b) {
    u64 d; asm("add.rn.f32x2 %0, %1, %2;" : "=l"(d) : "l"(a), "l"(b)); return d;
}

// ---------------- vector reduction helpers (sm_90+ red.v4) ------------------
__device__ __forceinline__ void red_add_v4(float4* addr, float a, float b, float c, float d) {
    asm volatile("red.global.add.v4.f32 [%0], {%1,%2,%3,%4};"
                 :: "l"(addr), "f"(a), "f"(b), "f"(c), "f"(d) : "memory");
}
__device__ __forceinline__ void red_add_f(float* addr, float v) {
    asm volatile("red.global.add.f32 [%0], %1;" :: "l"(addr), "f"(v) : "memory");
}

// ---------------- kernel 0: per-node precompute + zero-init ------------------
__global__ void __launch_bounds__(256) pre_kernel(
    const float* __restrict__ x, const float* __restrict__ pos,
    const float* __restrict__ w1, const float* __restrict__ b1)
{
    __shared__ float sw1[144];
    __shared__ float sb1[16];
    int t = threadIdx.x;
    if (t < 144) sw1[t] = w1[t];
    if (t < 16)  sb1[t] = b1[t];
    __syncthreads();

    int n = blockIdx.x * 256 + t;
    if (n >= N_NODES) return;

    float4 xv = reinterpret_cast<const float4*>(x)[n];

    float pdv[16], psv[16];
#pragma unroll
    for (int j = 0; j < 16; j++) {
        float a = sb1[j];
        a = fmaf(xv.x, sw1[0 * 16 + j], a);
        a = fmaf(xv.y, sw1[1 * 16 + j], a);
        a = fmaf(xv.z, sw1[2 * 16 + j], a);
        a = fmaf(xv.w, sw1[3 * 16 + j], a);
        pdv[j] = a;
        float b = xv.x * sw1[4 * 16 + j];
        b = fmaf(xv.y, sw1[5 * 16 + j], b);
        b = fmaf(xv.z, sw1[6 * 16 + j], b);
        b = fmaf(xv.w, sw1[7 * 16 + j], b);
        psv[j] = b;
    }
    float4* pdp = reinterpret_cast<float4*>(&g_pd[n * 4]);
    float4* psp = reinterpret_cast<float4*>(&g_ps[n * 4]);
#pragma unroll
    for (int k = 0; k < 4; k++) {
        pdp[k] = make_float4(pdv[4 * k], pdv[4 * k + 1], pdv[4 * k + 2], pdv[4 * k + 3]);
        psp[k] = make_float4(psv[4 * k], psv[4 * k + 1], psv[4 * k + 2], psv[4 * k + 3]);
    }

    g_pos4[n] = make_float4(pos[3 * n], pos[3 * n + 1], pos[3 * n + 2], 0.f);

    const float4 z = make_float4(0.f, 0.f, 0.f, 0.f);
#pragma unroll
    for (int k = 0; k < 4; k++) g_agg[n * 4 + k] = z;
    g_cnt[n] = 0.f;
    if (n < NUM_GRAPHS * 8) g_pooled[n] = z;
}

// ---------------- kernel 1: edge MLP + scatter -------------------------------
__global__ void __launch_bounds__(256) edge_kernel(
    const int* __restrict__ ei,
    const float* __restrict__ w1,   // need row 8 (dist row)
    const float* __restrict__ w2, const float* __restrict__ b2)
{
    __shared__ u64 sw18[8];       // w1 row 8, packed pairs
    __shared__ u64 sw2p[16 * 8];  // w2 packed pairs
    __shared__ u64 sb2p[8];

    int t = threadIdx.x;
    if (t < 8)   sw18[t] = pack2(w1[128 + 2 * t], w1[128 + 2 * t + 1]);
    if (t < 128) sw2p[t] = pack2(w2[2 * t], w2[2 * t + 1]);
    if (t >= 128 && t < 136) sb2p[t - 128] = pack2(b2[2 * (t - 128)], b2[2 * (t - 128) + 1]);
    __syncthreads();

    int e = blockIdx.x * 256 + t;
    if (e >= N_EDGES) return;

    int s = ei[e];
    int d = ei[N_EDGES + e];

    float4 pS = g_pos4[s];
    float4 pD = g_pos4[d];
    float rx = pS.x - pD.x, ry = pS.y - pD.y, rz = pS.z - pD.z;
    float dist = sqrtf(fmaf(rx, rx, fmaf(ry, ry, rz * rz)));
    u64 dd = pack2(dist, dist);

    // layer 1: hid = pd[dst] + ps[src] + dist * w1_row8   (all packed pairs)
    u64 hp[8];
#pragma unroll
    for (int k = 0; k < 4; k++) {
        ulonglong2 pdq = g_pd[d * 4 + k];
        ulonglong2 psq = g_ps[s * 4 + k];
        hp[2 * k + 0] = fma2(dd, sw18[2 * k + 0], add2(pdq.x, psq.x));
        hp[2 * k + 1] = fma2(dd, sw18[2 * k + 1], add2(pdq.y, psq.y));
    }

    // SiLU (scalar, MUFU)
    float h[16];
#pragma unroll
    for (int k = 0; k < 8; k++) {
        float a, b;
        unpack2(hp[k], a, b);
        h[2 * k + 0] = __fdividef(a, 1.f + __expf(-a));
        h[2 * k + 1] = __fdividef(b, 1.f + __expf(-b));
    }

    // layer 2: msg = hid @ w2 + b2   (packed FFMA2)
    u64 macc[8];
#pragma unroll
    for (int k = 0; k < 8; k++) macc[k] = sb2p[k];
#pragma unroll
    for (int i = 0; i < 16; i++) {
        u64 hh = pack2(h[i], h[i]);
#pragma unroll
        for (int k = 0; k < 8; k++) macc[k] = fma2(hh, sw2p[i * 8 + k], macc[k]);
    }

    float m[16];
#pragma unroll
    for (int k = 0; k < 8; k++) unpack2(macc[k], m[2 * k], m[2 * k + 1]);

    float4* aggp = &g_agg[d * 4];
    red_add_v4(aggp + 0, m[0],  m[1],  m[2],  m[3]);
    red_add_v4(aggp + 1, m[4],  m[5],  m[6],  m[7]);
    red_add_v4(aggp + 2, m[8],  m[9],  m[10], m[11]);
    red_add_v4(aggp + 3, m[12], m[13], m[14], m[15]);
    red_add_f(&g_cnt[d], 1.0f);
}

// ---------------- kernel 2: node mean/relu + softmax pooling ----------------
__global__ void __launch_bounds__(256) node_kernel(
    const int* __restrict__ batch,
    const float* __restrict__ pool_w, const float* __restrict__ pool_b,
    float* __restrict__ out_s)
{
    int n = blockIdx.x * blockDim.x + threadIdx.x;
    if (n >= N_NODES) return;

    float4 a0 = g_agg[n * 4 + 0];
    float4 a1 = g_agg[n * 4 + 1];
    float4 a2 = g_agg[n * 4 + 2];
    float4 a3 = g_agg[n * 4 + 3];
    float cnt = fmaxf(g_cnt[n], 1.0f);
    float inv = __frcp_rn(cnt);

    float h[16];
    h[0]  = fmaxf(a0.x * inv, 0.f); h[1]  = fmaxf(a0.y * inv, 0.f);
    h[2]  = fmaxf(a0.z * inv, 0.f); h[3]  = fmaxf(a0.w * inv, 0.f);
    h[4]  = fmaxf(a1.x * inv, 0.f); h[5]  = fmaxf(a1.y * inv, 0.f);
    h[6]  = fmaxf(a1.z * inv, 0.f); h[7]  = fmaxf(a1.w * inv, 0.f);
    h[8]  = fmaxf(a2.x * inv, 0.f); h[9]  = fmaxf(a2.y * inv, 0.f);
    h[10] = fmaxf(a2.z * inv, 0.f); h[11] = fmaxf(a2.w * inv, 0.f);
    h[12] = fmaxf(a3.x * inv, 0.f); h[13] = fmaxf(a3.y * inv, 0.f);
    h[14] = fmaxf(a3.z * inv, 0.f); h[15] = fmaxf(a3.w * inv, 0.f);

    float l0 = pool_b[0], l1 = pool_b[1];
#pragma unroll
    for (int i = 0; i < 16; i++) {
        l0 = fmaf(h[i], pool_w[i * 2 + 0], l0);
        l1 = fmaf(h[i], pool_w[i * 2 + 1], l1);
    }
    float mm = fmaxf(l0, l1);
    float e0 = __expf(l0 - mm), e1 = __expf(l1 - mm);
    float is = __frcp_rn(e0 + e1);
    float s0 = e0 * is, s1 = e1 * is;

    reinterpret_cast<float2*>(out_s)[n] = make_float2(s0, s1);

    int g = batch[n];
    const unsigned full = 0xffffffffu;
    int g0 = __shfl_sync(full, g, 0);
    bool uni = __all_sync(full, g == g0);

    float v[32];
#pragma unroll
    for (int i = 0; i < 16; i++) { v[i] = s0 * h[i]; v[16 + i] = s1 * h[i]; }

    if (uni) {
        // warp-level segmented reduction: whole warp same graph
#pragma unroll
        for (int j = 0; j < 32; j++) {
            float sv = v[j];
            sv += __shfl_xor_sync(full, sv, 16);
            sv += __shfl_xor_sync(full, sv, 8);
            sv += __shfl_xor_sync(full, sv, 4);
            sv += __shfl_xor_sync(full, sv, 2);
            sv += __shfl_xor_sync(full, sv, 1);
            v[j] = sv;
        }
        int lane = threadIdx.x & 31;
        float4* pp = &g_pooled[g0 * 8];
        switch (lane) {
            case 0: red_add_v4(pp + 0, v[0],  v[1],  v[2],  v[3]);  break;
            case 1: red_add_v4(pp + 1, v[4],  v[5],  v[6],  v[7]);  break;
            case 2: red_add_v4(pp + 2, v[8],  v[9],  v[10], v[11]); break;
            case 3: red_add_v4(pp + 3, v[12], v[13], v[14], v[15]); break;
            case 4: red_add_v4(pp + 4, v[16], v[17], v[18], v[19]); break;
            case 5: red_add_v4(pp + 5, v[20], v[21], v[22], v[23]); break;
            case 6: red_add_v4(pp + 6, v[24], v[25], v[26], v[27]); break;
            case 7: red_add_v4(pp + 7, v[28], v[29], v[30], v[31]); break;
            default: break;
        }
    } else {
        float4* pp = &g_pooled[g * 8];
        red_add_v4(pp + 0, v[0],  v[1],  v[2],  v[3]);
        red_add_v4(pp + 1, v[4],  v[5],  v[6],  v[7]);
        red_add_v4(pp + 2, v[8],  v[9],  v[10], v[11]);
        red_add_v4(pp + 3, v[12], v[13], v[14], v[15]);
        red_add_v4(pp + 4, v[16], v[17], v[18], v[19]);
        red_add_v4(pp + 5, v[20], v[21], v[22], v[23]);
        red_add_v4(pp + 6, v[24], v[25], v[26], v[27]);
        red_add_v4(pp + 7, v[28], v[29], v[30], v[31]);
    }
}

// ---------------- kernel 3: per-graph head ----------------------------------
__global__ void __launch_bounds__(64) graph_kernel(
    const float* __restrict__ toz_w, const float* __restrict__ toz_b,
    const float* __restrict__ vp_w1, const float* __restrict__ vp_b1,
    const float* __restrict__ vp_w2, const float* __restrict__ vp_b2,
    const float* __restrict__ bridge_w, const float* __restrict__ bridge_b,
    float* __restrict__ out_recon,   // (1024, 8, 4)
    float* __restrict__ out_z,       // (1024, 2, 4)
    float* __restrict__ out_forces,  // (1024, 2, 2)
    float* __restrict__ out_V)       // (1024, 1)
{
    int g = blockIdx.x * blockDim.x + threadIdx.x;
    if (g >= NUM_GRAPHS) return;

    float p[32];
    const float* pp = reinterpret_cast<const float*>(&g_pooled[g * 8]);
#pragma unroll
    for (int i = 0; i < 32; i++) p[i] = pp[i];

    // z = pooled @ toz_w + toz_b   (2x16 @ 16x4)
    float z[8];
#pragma unroll
    for (int k = 0; k < 2; k++) {
#pragma unroll
        for (int c = 0; c < 4; c++) {
            float acc = __ldg(&toz_b[c]);
#pragma unroll
            for (int i = 0; i < 16; i++)
                acc = fmaf(p[k * 16 + i], __ldg(&toz_w[i * 4 + c]), acc);
            z[k * 4 + c] = acc;
        }
    }
#pragma unroll
    for (int i = 0; i < 8; i++) out_z[g * 8 + i] = z[i];

    // recon = zflat(8) @ bridge_w(8,32) + b
#pragma unroll
    for (int j = 0; j < 32; j++) {
        float acc = __ldg(&bridge_b[j]);
#pragma unroll
        for (int i = 0; i < 8; i++)
            acc = fmaf(z[i], __ldg(&bridge_w[i * 32 + j]), acc);
        out_recon[g * 32 + j] = acc;
    }

    // potential + analytic forces (K=2 -> single pair)
    float dx = z[0] - z[4];
    float dy = z[1] - z[5];
    float dist = sqrtf(dx * dx + dy * dy + 1e-6f);

    float V = __ldg(&vp_b2[0]);
    float fp = 0.f;
#pragma unroll
    for (int j = 0; j < 32; j++) {
        float w1 = __ldg(&vp_w1[j]);
        float w2 = __ldg(&vp_w2[j]);
        float t = fmaf(dist, w1, __ldg(&vp_b1[j]));
        // stable softplus with fast math: max(t,0) + log(1 + exp(-|t|))
        float u  = __expf(-fabsf(t));
        float sp = fmaxf(t, 0.f) + __logf(1.f + u);
        V = fmaf(sp, w2, V);
        float sig = __frcp_rn(1.f + __expf(-t));
        fp = fmaf(sig * w1, w2, fp);
    }
    float c = fp / dist;
    out_forces[g * 4 + 0] = -c * dx;
    out_forces[g * 4 + 1] = -c * dy;
    out_forces[g * 4 + 2] =  c * dx;
    out_forces[g * 4 + 3] =  c * dy;
    out_V[g] = V;
}

// ---------------- launch -----------------------------------------------------
extern "C" void kernel_launch(void* const* d_in, const int* in_sizes, int n_in,
                              void* d_out, int out_size)
{
    const float* x        = (const float*)d_in[0];
    const float* pos      = (const float*)d_in[1];
    const int*   ei       = (const int*)  d_in[2];
    const int*   batch    = (const int*)  d_in[3];
    const float* enc_w1   = (const float*)d_in[4];
    const float* enc_b1   = (const float*)d_in[5];
    const float* enc_w2   = (const float*)d_in[6];
    const float* enc_b2   = (const float*)d_in[7];
    const float* pool_w   = (const float*)d_in[8];
    const float* pool_b   = (const float*)d_in[9];
    const float* toz_w    = (const float*)d_in[10];
    const float* toz_b    = (const float*)d_in[11];
    const float* vp_w1    = (const float*)d_in[12];
    const float* vp_b1    = (const float*)d_in[13];
    const float* vp_w2    = (const float*)d_in[14];
    const float* vp_b2    = (const float*)d_in[15];
    const float* bridge_w = (const float*)d_in[16];
    const float* bridge_b = (const float*)d_in[17];

    float* out = (float*)d_out;
    float* out_recon  = out;                 // 1024*8*4 = 32768
    float* out_z      = out + 32768;         // 1024*2*4 =  8192
    float* out_s      = out + 40960;         // 262144*2 = 524288
    float* out_forces = out + 565248;        // 1024*2*2 =  4096
    float* out_V      = out + 569344;        // 1024

    pre_kernel<<<N_NODES / 256, 256>>>(x, pos, enc_w1, enc_b1);

    edge_kernel<<<N_EDGES / 256, 256>>>(ei, enc_w1, enc_w2, enc_b2);

    node_kernel<<<N_NODES / 256, 256>>>(batch, pool_w, pool_b, out_s);

    graph_kernel<<<NUM_GRAPHS / 64, 64>>>(toz_w, toz_b, vp_w1, vp_b1, vp_w2, vp_b2,
                                          bridge_w, bridge_b,
                                          out_recon, out_z, out_forces, out_V);
}

// round 7
// speedup vs baseline: 2.0218x; 2.0218x over previous
#include <cuda_runtime.h>

#define N_NODES    262144
#define N_EDGES    4194304
#define NUM_GRAPHS 1024

typedef unsigned long long u64;

// ---------------- scratch (device globals; no allocations allowed) ----------
__device__ float4 g_pos4[N_NODES];          // padded pos
__device__ float4 g_agg[N_NODES * 4];       // agg: (N_NODES, 16) f32
__device__ float  g_cnt[N_NODES];           // cnt
__device__ float4 g_pooled[NUM_GRAPHS * 8]; // pooled: (NUM_GRAPHS, 2, 16)

// ---------------- packed f32x2 helpers (Blackwell FFMA2 path) ----------------
__device__ __forceinline__ u64 pack2(float lo, float hi) {
    u64 r; asm("mov.b64 %0, {%1,%2};" : "=l"(r) : "f"(lo), "f"(hi)); return r;
}
__device__ __forceinline__ void unpack2(u64 v, float& lo, float& hi) {
    asm("mov.b64 {%0,%1}, %2;" : "=f"(lo), "=f"(hi) : "l"(v));
}
__device__ __forceinline__ u64 fma2(u64 a, u64 b, u64 c) {
    u64 d; asm("fma.rn.f32x2 %0, %1, %2, %3;" : "=l"(d) : "l"(a), "l"(b), "l"(c)); return d;
}

// SiLU via single-MUFU tanh: silu(u) = 0.5u * (1 + tanh(u/2))
__device__ __forceinline__ float silu_f(float u) {
    float hu = 0.5f * u;
    float th; asm("tanh.approx.f32 %0, %1;" : "=f"(th) : "f"(hu));
    return fmaf(hu, th, hu);
}

// ---------------- vector reduction helpers (sm_90+ red.v4) ------------------
__device__ __forceinline__ void red_add_v4(float4* addr, float a, float b, float c, float d) {
    asm volatile("red.global.add.v4.f32 [%0], {%1,%2,%3,%4};"
                 :: "l"(addr), "f"(a), "f"(b), "f"(c), "f"(d) : "memory");
}
__device__ __forceinline__ void red_add_f(float* addr, float v) {
    asm volatile("red.global.add.f32 [%0], %1;" :: "l"(addr), "f"(v) : "memory");
}

// ---------------- kernel 0: pos4 pad + zero-init -----------------------------
__global__ void __launch_bounds__(256) pre_kernel(const float* __restrict__ pos)
{
    int n = blockIdx.x * 256 + threadIdx.x;
    if (n >= N_NODES) return;
    g_pos4[n] = make_float4(pos[3 * n], pos[3 * n + 1], pos[3 * n + 2], 0.f);
    const float4 z = make_float4(0.f, 0.f, 0.f, 0.f);
#pragma unroll
    for (int k = 0; k < 4; k++) g_agg[n * 4 + k] = z;
    g_cnt[n] = 0.f;
    if (n < NUM_GRAPHS * 8) g_pooled[n] = z;
}

// ---------------- kernel 1: edge MLP + scatter (FFMA2) -----------------------
__global__ void __launch_bounds__(256) edge_kernel(
    const float* __restrict__ x,
    const int* __restrict__ ei,
    const float* __restrict__ w1, const float* __restrict__ b1,
    const float* __restrict__ w2, const float* __restrict__ b2)
{
    __shared__ u64 sw1p[72];   // 9 rows x 8 channel-pairs
    __shared__ u64 sb1p[8];
    __shared__ u64 sw2p[128];  // 16 rows x 8 channel-pairs
    __shared__ u64 sb2p[8];

    int t = threadIdx.x;
    if (t < 72)                 sw1p[t]       = pack2(w1[2 * t],         w1[2 * t + 1]);
    else if (t < 80)            sb1p[t - 72]  = pack2(b1[2 * (t - 72)],  b1[2 * (t - 72) + 1]);
    else if (t < 208)           sw2p[t - 80]  = pack2(w2[2 * (t - 80)],  w2[2 * (t - 80) + 1]);
    else if (t < 216)           sb2p[t - 208] = pack2(b2[2 * (t - 208)], b2[2 * (t - 208) + 1]);
    __syncthreads();

    int e = blockIdx.x * 256 + t;
    if (e >= N_EDGES) return;

    int s = ei[e];
    int d = ei[N_EDGES + e];

    float4 pS = g_pos4[s];
    float4 pD = g_pos4[d];
    float rx = pS.x - pD.x, ry = pS.y - pD.y, rz = pS.z - pD.z;
    float dist = sqrtf(fmaf(rx, rx, fmaf(ry, ry, rz * rz)));

    float4 xd = reinterpret_cast<const float4*>(x)[d];
    float4 xs = reinterpret_cast<const float4*>(x)[s];

    float feat[9];
    feat[0] = xd.x; feat[1] = xd.y; feat[2] = xd.z; feat[3] = xd.w;
    feat[4] = xs.x; feat[5] = xs.y; feat[6] = xs.z; feat[7] = xs.w;
    feat[8] = dist;

    // layer 1: 72 FFMA2
    u64 acc[8];
#pragma unroll
    for (int j = 0; j < 8; j++) acc[j] = sb1p[j];
#pragma unroll
    for (int i = 0; i < 9; i++) {
        u64 ff = pack2(feat[i], feat[i]);
#pragma unroll
        for (int j = 0; j < 8; j++) acc[j] = fma2(ff, sw1p[i * 8 + j], acc[j]);
    }

    // SiLU (single MUFU each)
    float h[16];
#pragma unroll
    for (int k = 0; k < 8; k++) {
        float a, b;
        unpack2(acc[k], a, b);
        h[2 * k + 0] = silu_f(a);
        h[2 * k + 1] = silu_f(b);
    }

    // layer 2: 128 FFMA2
    u64 m[8];
#pragma unroll
    for (int j = 0; j < 8; j++) m[j] = sb2p[j];
#pragma unroll
    for (int i = 0; i < 16; i++) {
        u64 hh = pack2(h[i], h[i]);
#pragma unroll
        for (int j = 0; j < 8; j++) m[j] = fma2(hh, sw2p[i * 8 + j], m[j]);
    }

    float mv[16];
#pragma unroll
    for (int k = 0; k < 8; k++) unpack2(m[k], mv[2 * k], mv[2 * k + 1]);

    float4* aggp = &g_agg[d * 4];
    red_add_v4(aggp + 0, mv[0],  mv[1],  mv[2],  mv[3]);
    red_add_v4(aggp + 1, mv[4],  mv[5],  mv[6],  mv[7]);
    red_add_v4(aggp + 2, mv[8],  mv[9],  mv[10], mv[11]);
    red_add_v4(aggp + 3, mv[12], mv[13], mv[14], mv[15]);
    red_add_f(&g_cnt[d], 1.0f);
}

// ---------------- kernel 2: node mean/relu + softmax pooling ----------------
__global__ void __launch_bounds__(256) node_kernel(
    const int* __restrict__ batch,
    const float* __restrict__ pool_w, const float* __restrict__ pool_b,
    float* __restrict__ out_s)
{
    int n = blockIdx.x * blockDim.x + threadIdx.x;
    if (n >= N_NODES) return;

    float4 a0 = g_agg[n * 4 + 0];
    float4 a1 = g_agg[n * 4 + 1];
    float4 a2 = g_agg[n * 4 + 2];
    float4 a3 = g_agg[n * 4 + 3];
    float cnt = fmaxf(g_cnt[n], 1.0f);
    float inv = __frcp_rn(cnt);

    float h[16];
    h[0]  = fmaxf(a0.x * inv, 0.f); h[1]  = fmaxf(a0.y * inv, 0.f);
    h[2]  = fmaxf(a0.z * inv, 0.f); h[3]  = fmaxf(a0.w * inv, 0.f);
    h[4]  = fmaxf(a1.x * inv, 0.f); h[5]  = fmaxf(a1.y * inv, 0.f);
    h[6]  = fmaxf(a1.z * inv, 0.f); h[7]  = fmaxf(a1.w * inv, 0.f);
    h[8]  = fmaxf(a2.x * inv, 0.f); h[9]  = fmaxf(a2.y * inv, 0.f);
    h[10] = fmaxf(a2.z * inv, 0.f); h[11] = fmaxf(a2.w * inv, 0.f);
    h[12] = fmaxf(a3.x * inv, 0.f); h[13] = fmaxf(a3.y * inv, 0.f);
    h[14] = fmaxf(a3.z * inv, 0.f); h[15] = fmaxf(a3.w * inv, 0.f);

    float l0 = pool_b[0], l1 = pool_b[1];
#pragma unroll
    for (int i = 0; i < 16; i++) {
        l0 = fmaf(h[i], pool_w[i * 2 + 0], l0);
        l1 = fmaf(h[i], pool_w[i * 2 + 1], l1);
    }
    float mm = fmaxf(l0, l1);
    float e0 = __expf(l0 - mm), e1 = __expf(l1 - mm);
    float is = __frcp_rn(e0 + e1);
    float s0 = e0 * is, s1 = e1 * is;

    reinterpret_cast<float2*>(out_s)[n] = make_float2(s0, s1);

    int g = batch[n];
    const unsigned full = 0xffffffffu;
    int g0 = __shfl_sync(full, g, 0);
    bool uni = __all_sync(full, g == g0);

    float v[32];
#pragma unroll
    for (int i = 0; i < 16; i++) { v[i] = s0 * h[i]; v[16 + i] = s1 * h[i]; }

    if (uni) {
#pragma unroll
        for (int j = 0; j < 32; j++) {
            float sv = v[j];
            sv += __shfl_xor_sync(full, sv, 16);
            sv += __shfl_xor_sync(full, sv, 8);
            sv += __shfl_xor_sync(full, sv, 4);
            sv += __shfl_xor_sync(full, sv, 2);
            sv += __shfl_xor_sync(full, sv, 1);
            v[j] = sv;
        }
        int lane = threadIdx.x & 31;
        float4* pp = &g_pooled[g0 * 8];
        switch (lane) {
            case 0: red_add_v4(pp + 0, v[0],  v[1],  v[2],  v[3]);  break;
            case 1: red_add_v4(pp + 1, v[4],  v[5],  v[6],  v[7]);  break;
            case 2: red_add_v4(pp + 2, v[8],  v[9],  v[10], v[11]); break;
            case 3: red_add_v4(pp + 3, v[12], v[13], v[14], v[15]); break;
            case 4: red_add_v4(pp + 4, v[16], v[17], v[18], v[19]); break;
            case 5: red_add_v4(pp + 5, v[20], v[21], v[22], v[23]); break;
            case 6: red_add_v4(pp + 6, v[24], v[25], v[26], v[27]); break;
            case 7: red_add_v4(pp + 7, v[28], v[29], v[30], v[31]); break;
            default: break;
        }
    } else {
        float4* pp = &g_pooled[g * 8];
        red_add_v4(pp + 0, v[0],  v[1],  v[2],  v[3]);
        red_add_v4(pp + 1, v[4],  v[5],  v[6],  v[7]);
        red_add_v4(pp + 2, v[8],  v[9],  v[10], v[11]);
        red_add_v4(pp + 3, v[12], v[13], v[14], v[15]);
        red_add_v4(pp + 4, v[16], v[17], v[18], v[19]);
        red_add_v4(pp + 5, v[20], v[21], v[22], v[23]);
        red_add_v4(pp + 6, v[24], v[25], v[26], v[27]);
        red_add_v4(pp + 7, v[28], v[29], v[30], v[31]);
    }
}

// ---------------- kernel 3: per-graph head (one warp per graph) -------------
__global__ void __launch_bounds__(32) graph_kernel(
    const float* __restrict__ toz_w, const float* __restrict__ toz_b,
    const float* __restrict__ vp_w1, const float* __restrict__ vp_b1,
    const float* __restrict__ vp_w2, const float* __restrict__ vp_b2,
    const float* __restrict__ bridge_w, const float* __restrict__ bridge_b,
    float* __restrict__ out_recon,   // (1024, 8, 4)
    float* __restrict__ out_z,       // (1024, 2, 4)
    float* __restrict__ out_forces,  // (1024, 2, 2)
    float* __restrict__ out_V)       // (1024, 1)
{
    const unsigned full = 0xffffffffu;
    int g = blockIdx.x;
    int l = threadIdx.x;
    int k = l >> 4;         // 0 or 1 (pooled row)
    int idx = l & 15;       // feature index within row

    float p = reinterpret_cast<const float*>(&g_pooled[g * 8])[l];

    // z[k*4+c] = sum_idx p[k,idx] * toz_w[idx,c] + b ; reduce within 16-lane group
    float z[8];
#pragma unroll
    for (int c = 0; c < 4; c++) {
        float prod = p * toz_w[idx * 4 + c];
        prod += __shfl_xor_sync(full, prod, 8);
        prod += __shfl_xor_sync(full, prod, 4);
        prod += __shfl_xor_sync(full, prod, 2);
        prod += __shfl_xor_sync(full, prod, 1);
        float zo = prod + toz_b[c];           // own-group z
        float zx = __shfl_xor_sync(full, zo, 16); // other-group z
        z[k * 4 + c] = zo;
        z[(1 - k) * 4 + c] = zx;
    }

    if (l < 8) out_z[g * 8 + l] = z[l];

    // recon: lane l computes output column l
    {
        float acc = bridge_b[l];
#pragma unroll
        for (int i = 0; i < 8; i++)
            acc = fmaf(z[i], bridge_w[i * 32 + l], acc);
        out_recon[g * 32 + l] = acc;
    }

    // potential + analytic forces; lane l handles hidden unit l of the vp MLP
    float dx = z[0] - z[4];
    float dy = z[1] - z[5];
    float dist = sqrtf(dx * dx + dy * dy + 1e-6f);

    float w1 = vp_w1[l];
    float w2 = vp_w2[l];
    float tt = fmaf(dist, w1, vp_b1[l]);
    float u  = __expf(-fabsf(tt));
    float sp = fmaxf(tt, 0.f) + __logf(1.f + u);
    float Vp = sp * w2;
    float sig = __frcp_rn(1.f + __expf(-tt));
    float fpp = sig * w1 * w2;

#pragma unroll
    for (int off = 16; off >= 1; off >>= 1) {
        Vp  += __shfl_xor_sync(full, Vp,  off);
        fpp += __shfl_xor_sync(full, fpp, off);
    }

    if (l == 0) {
        float c = fpp / dist;
        out_forces[g * 4 + 0] = -c * dx;
        out_forces[g * 4 + 1] = -c * dy;
        out_forces[g * 4 + 2] =  c * dx;
        out_forces[g * 4 + 3] =  c * dy;
        out_V[g] = Vp + vp_b2[0];
    }
}

// ---------------- launch -----------------------------------------------------
extern "C" void kernel_launch(void* const* d_in, const int* in_sizes, int n_in,
                              void* d_out, int out_size)
{
    const float* x        = (const float*)d_in[0];
    const float* pos      = (const float*)d_in[1];
    const int*   ei       = (const int*)  d_in[2];
    const int*   batch    = (const int*)  d_in[3];
    const float* enc_w1   = (const float*)d_in[4];
    const float* enc_b1   = (const float*)d_in[5];
    const float* enc_w2   = (const float*)d_in[6];
    const float* enc_b2   = (const float*)d_in[7];
    const float* pool_w   = (const float*)d_in[8];
    const float* pool_b   = (const float*)d_in[9];
    const float* toz_w    = (const float*)d_in[10];
    const float* toz_b    = (const float*)d_in[11];
    const float* vp_w1    = (const float*)d_in[12];
    const float* vp_b1    = (const float*)d_in[13];
    const float* vp_w2    = (const float*)d_in[14];
    const float* vp_b2    = (const float*)d_in[15];
    const float* bridge_w = (const float*)d_in[16];
    const float* bridge_b = (const float*)d_in[17];

    float* out = (float*)d_out;
    float* out_recon  = out;                 // 1024*8*4 = 32768
    float* out_z      = out + 32768;         // 1024*2*4 =  8192
    float* out_s      = out + 40960;         // 262144*2 = 524288
    float* out_forces = out + 565248;        // 1024*2*2 =  4096
    float* out_V      = out + 569344;        // 1024

    pre_kernel<<<N_NODES / 256, 256>>>(pos);

    edge_kernel<<<N_EDGES / 256, 256>>>(x, ei, enc_w1, enc_b1, enc_w2, enc_b2);

    node_kernel<<<N_NODES / 256, 256>>>(batch, pool_w, pool_b, out_s);

    graph_kernel<<<NUM_GRAPHS, 32>>>(toz_w, toz_b, vp_w1, vp_b1, vp_w2, vp_b2,
                                     bridge_w, bridge_b,
                                     out_recon, out_z, out_forces, out_V);
}

// round 8
// speedup vs baseline: 2.2287x; 1.1023x over previous
#include <cuda_runtime.h>

#define N_NODES    262144
#define N_EDGES    4194304
#define NUM_GRAPHS 1024

typedef unsigned long long u64;

// ---------------- scratch (device globals; no allocations allowed) ----------
struct __align__(32) NodeRec {
    float4 x;    // node features
    float4 pos;  // padded position (w unused)
};
__device__ NodeRec g_rec[N_NODES];          // packed per-node record (32B, one sector-pair)
__device__ float4  g_agg[N_NODES * 4];      // agg: (N_NODES, 16) f32
__device__ float   g_cnt[N_NODES];          // cnt
__device__ float4  g_pooled[NUM_GRAPHS * 8];// pooled: (NUM_GRAPHS, 2, 16)

// ---------------- packed f32x2 helpers (Blackwell FFMA2 path) ----------------
__device__ __forceinline__ u64 pack2(float lo, float hi) {
    u64 r; asm("mov.b64 %0, {%1,%2};" : "=l"(r) : "f"(lo), "f"(hi)); return r;
}
__device__ __forceinline__ void unpack2(u64 v, float& lo, float& hi) {
    asm("mov.b64 {%0,%1}, %2;" : "=f"(lo), "=f"(hi) : "l"(v));
}
__device__ __forceinline__ u64 fma2(u64 a, u64 b, u64 c) {
    u64 d; asm("fma.rn.f32x2 %0, %1, %2, %3;" : "=l"(d) : "l"(a), "l"(b), "l"(c)); return d;
}

// SiLU via single-MUFU tanh: silu(u) = 0.5u * (1 + tanh(u/2))
__device__ __forceinline__ float silu_f(float u) {
    float hu = 0.5f * u;
    float th; asm("tanh.approx.f32 %0, %1;" : "=f"(th) : "f"(hu));
    return fmaf(hu, th, hu);
}

// ---------------- vector reduction helpers (sm_90+ red.v4) ------------------
__device__ __forceinline__ void red_add_v4(float4* addr, float a, float b, float c, float d) {
    asm volatile("red.global.add.v4.f32 [%0], {%1,%2,%3,%4};"
                 :: "l"(addr), "f"(a), "f"(b), "f"(c), "f"(d) : "memory");
}
__device__ __forceinline__ void red_add_f(float* addr, float v) {
    asm volatile("red.global.add.f32 [%0], %1;" :: "l"(addr), "f"(v) : "memory");
}

// ---------------- kernel 0: build packed record + zero-init ------------------
__global__ void __launch_bounds__(256) pre_kernel(
    const float* __restrict__ x, const float* __restrict__ pos)
{
    int n = blockIdx.x * 256 + threadIdx.x;
    if (n >= N_NODES) return;
    NodeRec r;
    r.x   = reinterpret_cast<const float4*>(x)[n];
    r.pos = make_float4(pos[3 * n], pos[3 * n + 1], pos[3 * n + 2], 0.f);
    g_rec[n] = r;

    const float4 z = make_float4(0.f, 0.f, 0.f, 0.f);
#pragma unroll
    for (int k = 0; k < 4; k++) g_agg[n * 4 + k] = z;
    g_cnt[n] = 0.f;
    if (n < NUM_GRAPHS * 8) g_pooled[n] = z;
}

// ---------------- kernel 1: edge MLP + scatter (FFMA2) -----------------------
__global__ void __launch_bounds__(256) edge_kernel(
    const int* __restrict__ ei,
    const float* __restrict__ w1, const float* __restrict__ b1,
    const float* __restrict__ w2, const float* __restrict__ b2)
{
    __shared__ u64 sw1p[72];   // 9 rows x 8 channel-pairs
    __shared__ u64 sb1p[8];
    __shared__ u64 sw2p[128];  // 16 rows x 8 channel-pairs
    __shared__ u64 sb2p[8];

    int t = threadIdx.x;
    if (t < 72)                 sw1p[t]       = pack2(w1[2 * t],         w1[2 * t + 1]);
    else if (t < 80)            sb1p[t - 72]  = pack2(b1[2 * (t - 72)],  b1[2 * (t - 72) + 1]);
    else if (t < 208)           sw2p[t - 80]  = pack2(w2[2 * (t - 80)],  w2[2 * (t - 80) + 1]);
    else if (t < 216)           sb2p[t - 208] = pack2(b2[2 * (t - 208)], b2[2 * (t - 208) + 1]);
    __syncthreads();

    int e = blockIdx.x * 256 + t;
    if (e >= N_EDGES) return;

    int s = ei[e];
    int d = ei[N_EDGES + e];

    // two 32B record reads (each = 2x LDG.128 on the same 128B line)
    NodeRec rs = g_rec[s];
    NodeRec rd = g_rec[d];

    float rx = rs.pos.x - rd.pos.x;
    float ry = rs.pos.y - rd.pos.y;
    float rz = rs.pos.z - rd.pos.z;
    float dist = sqrtf(fmaf(rx, rx, fmaf(ry, ry, rz * rz)));

    float feat[9];
    feat[0] = rd.x.x; feat[1] = rd.x.y; feat[2] = rd.x.z; feat[3] = rd.x.w;
    feat[4] = rs.x.x; feat[5] = rs.x.y; feat[6] = rs.x.z; feat[7] = rs.x.w;
    feat[8] = dist;

    // layer 1: 72 FFMA2
    u64 acc[8];
#pragma unroll
    for (int j = 0; j < 8; j++) acc[j] = sb1p[j];
#pragma unroll
    for (int i = 0; i < 9; i++) {
        u64 ff = pack2(feat[i], feat[i]);
#pragma unroll
        for (int j = 0; j < 8; j++) acc[j] = fma2(ff, sw1p[i * 8 + j], acc[j]);
    }

    // SiLU (single MUFU each)
    float h[16];
#pragma unroll
    for (int k = 0; k < 8; k++) {
        float a, b;
        unpack2(acc[k], a, b);
        h[2 * k + 0] = silu_f(a);
        h[2 * k + 1] = silu_f(b);
    }

    // layer 2: 128 FFMA2
    u64 m[8];
#pragma unroll
    for (int j = 0; j < 8; j++) m[j] = sb2p[j];
#pragma unroll
    for (int i = 0; i < 16; i++) {
        u64 hh = pack2(h[i], h[i]);
#pragma unroll
        for (int j = 0; j < 8; j++) m[j] = fma2(hh, sw2p[i * 8 + j], m[j]);
    }

    float mv[16];
#pragma unroll
    for (int k = 0; k < 8; k++) unpack2(m[k], mv[2 * k], mv[2 * k + 1]);

    float4* aggp = &g_agg[d * 4];
    red_add_v4(aggp + 0, mv[0],  mv[1],  mv[2],  mv[3]);
    red_add_v4(aggp + 1, mv[4],  mv[5],  mv[6],  mv[7]);
    red_add_v4(aggp + 2, mv[8],  mv[9],  mv[10], mv[11]);
    red_add_v4(aggp + 3, mv[12], mv[13], mv[14], mv[15]);
    red_add_f(&g_cnt[d], 1.0f);
}

// ---------------- kernel 2: node mean/relu + softmax pooling ----------------
__global__ void __launch_bounds__(256) node_kernel(
    const int* __restrict__ batch,
    const float* __restrict__ pool_w, const float* __restrict__ pool_b,
    float* __restrict__ out_s)
{
    int n = blockIdx.x * blockDim.x + threadIdx.x;
    if (n >= N_NODES) return;

    float4 a0 = g_agg[n * 4 + 0];
    float4 a1 = g_agg[n * 4 + 1];
    float4 a2 = g_agg[n * 4 + 2];
    float4 a3 = g_agg[n * 4 + 3];
    float cnt = fmaxf(g_cnt[n], 1.0f);
    float inv = __frcp_rn(cnt);

    float h[16];
    h[0]  = fmaxf(a0.x * inv, 0.f); h[1]  = fmaxf(a0.y * inv, 0.f);
    h[2]  = fmaxf(a0.z * inv, 0.f); h[3]  = fmaxf(a0.w * inv, 0.f);
    h[4]  = fmaxf(a1.x * inv, 0.f); h[5]  = fmaxf(a1.y * inv, 0.f);
    h[6]  = fmaxf(a1.z * inv, 0.f); h[7]  = fmaxf(a1.w * inv, 0.f);
    h[8]  = fmaxf(a2.x * inv, 0.f); h[9]  = fmaxf(a2.y * inv, 0.f);
    h[10] = fmaxf(a2.z * inv, 0.f); h[11] = fmaxf(a2.w * inv, 0.f);
    h[12] = fmaxf(a3.x * inv, 0.f); h[13] = fmaxf(a3.y * inv, 0.f);
    h[14] = fmaxf(a3.z * inv, 0.f); h[15] = fmaxf(a3.w * inv, 0.f);

    float l0 = pool_b[0], l1 = pool_b[1];
#pragma unroll
    for (int i = 0; i < 16; i++) {
        l0 = fmaf(h[i], pool_w[i * 2 + 0], l0);
        l1 = fmaf(h[i], pool_w[i * 2 + 1], l1);
    }
    float mm = fmaxf(l0, l1);
    float e0 = __expf(l0 - mm), e1 = __expf(l1 - mm);
    float is = __frcp_rn(e0 + e1);
    float s0 = e0 * is, s1 = e1 * is;

    reinterpret_cast<float2*>(out_s)[n] = make_float2(s0, s1);

    int g = batch[n];
    const unsigned full = 0xffffffffu;
    int g0 = __shfl_sync(full, g, 0);
    bool uni = __all_sync(full, g == g0);

    float v[32];
#pragma unroll
    for (int i = 0; i < 16; i++) { v[i] = s0 * h[i]; v[16 + i] = s1 * h[i]; }

    if (uni) {
#pragma unroll
        for (int j = 0; j < 32; j++) {
            float sv = v[j];
            sv += __shfl_xor_sync(full, sv, 16);
            sv += __shfl_xor_sync(full, sv, 8);
            sv += __shfl_xor_sync(full, sv, 4);
            sv += __shfl_xor_sync(full, sv, 2);
            sv += __shfl_xor_sync(full, sv, 1);
            v[j] = sv;
        }
        int lane = threadIdx.x & 31;
        float4* pp = &g_pooled[g0 * 8];
        switch (lane) {
            case 0: red_add_v4(pp + 0, v[0],  v[1],  v[2],  v[3]);  break;
            case 1: red_add_v4(pp + 1, v[4],  v[5],  v[6],  v[7]);  break;
            case 2: red_add_v4(pp + 2, v[8],  v[9],  v[10], v[11]); break;
            case 3: red_add_v4(pp + 3, v[12], v[13], v[14], v[15]); break;
            case 4: red_add_v4(pp + 4, v[16], v[17], v[18], v[19]); break;
            case 5: red_add_v4(pp + 5, v[20], v[21], v[22], v[23]); break;
            case 6: red_add_v4(pp + 6, v[24], v[25], v[26], v[27]); break;
            case 7: red_add_v4(pp + 7, v[28], v[29], v[30], v[31]); break;
            default: break;
        }
    } else {
        float4* pp = &g_pooled[g * 8];
        red_add_v4(pp + 0, v[0],  v[1],  v[2],  v[3]);
        red_add_v4(pp + 1, v[4],  v[5],  v[6],  v[7]);
        red_add_v4(pp + 2, v[8],  v[9],  v[10], v[11]);
        red_add_v4(pp + 3, v[12], v[13], v[14], v[15]);
        red_add_v4(pp + 4, v[16], v[17], v[18], v[19]);
        red_add_v4(pp + 5, v[20], v[21], v[22], v[23]);
        red_add_v4(pp + 6, v[24], v[25], v[26], v[27]);
        red_add_v4(pp + 7, v[28], v[29], v[30], v[31]);
    }
}

// ---------------- kernel 3: per-graph head (one warp per graph) -------------
__global__ void __launch_bounds__(32) graph_kernel(
    const float* __restrict__ toz_w, const float* __restrict__ toz_b,
    const float* __restrict__ vp_w1, const float* __restrict__ vp_b1,
    const float* __restrict__ vp_w2, const float* __restrict__ vp_b2,
    const float* __restrict__ bridge_w, const float* __restrict__ bridge_b,
    float* __restrict__ out_recon,   // (1024, 8, 4)
    float* __restrict__ out_z,       // (1024, 2, 4)
    float* __restrict__ out_forces,  // (1024, 2, 2)
    float* __restrict__ out_V)       // (1024, 1)
{
    const unsigned full = 0xffffffffu;
    int g = blockIdx.x;
    int l = threadIdx.x;
    int k = l >> 4;         // 0 or 1 (pooled row)
    int idx = l & 15;       // feature index within row

    float p = reinterpret_cast<const float*>(&g_pooled[g * 8])[l];

    // z[k*4+c] = sum_idx p[k,idx] * toz_w[idx,c] + b ; reduce within 16-lane group
    float z[8];
#pragma unroll
    for (int c = 0; c < 4; c++) {
        float prod = p * toz_w[idx * 4 + c];
        prod += __shfl_xor_sync(full, prod, 8);
        prod += __shfl_xor_sync(full, prod, 4);
        prod += __shfl_xor_sync(full, prod, 2);
        prod += __shfl_xor_sync(full, prod, 1);
        float zo = prod + toz_b[c];               // own-group z
        float zx = __shfl_xor_sync(full, zo, 16); // other-group z
        z[k * 4 + c] = zo;
        z[(1 - k) * 4 + c] = zx;
    }

    if (l < 8) out_z[g * 8 + l] = z[l];

    // recon: lane l computes output column l
    {
        float acc = bridge_b[l];
#pragma unroll
        for (int i = 0; i < 8; i++)
            acc = fmaf(z[i], bridge_w[i * 32 + l], acc);
        out_recon[g * 32 + l] = acc;
    }

    // potential + analytic forces; lane l handles hidden unit l of the vp MLP
    float dx = z[0] - z[4];
    float dy = z[1] - z[5];
    float dist = sqrtf(dx * dx + dy * dy + 1e-6f);

    float w1 = vp_w1[l];
    float w2 = vp_w2[l];
    float tt = fmaf(dist, w1, vp_b1[l]);
    float u  = __expf(-fabsf(tt));
    float sp = fmaxf(tt, 0.f) + __logf(1.f + u);
    float Vp = sp * w2;
    float sig = __frcp_rn(1.f + __expf(-tt));
    float fpp = sig * w1 * w2;

#pragma unroll
    for (int off = 16; off >= 1; off >>= 1) {
        Vp  += __shfl_xor_sync(full, Vp,  off);
        fpp += __shfl_xor_sync(full, fpp, off);
    }

    if (l == 0) {
        float c = fpp / dist;
        out_forces[g * 4 + 0] = -c * dx;
        out_forces[g * 4 + 1] = -c * dy;
        out_forces[g * 4 + 2] =  c * dx;
        out_forces[g * 4 + 3] =  c * dy;
        out_V[g] = Vp + vp_b2[0];
    }
}

// ---------------- launch -----------------------------------------------------
extern "C" void kernel_launch(void* const* d_in, const int* in_sizes, int n_in,
                              void* d_out, int out_size)
{
    const float* x        = (const float*)d_in[0];
    const float* pos      = (const float*)d_in[1];
    const int*   ei       = (const int*)  d_in[2];
    const int*   batch    = (const int*)  d_in[3];
    const float* enc_w1   = (const float*)d_in[4];
    const float* enc_b1   = (const float*)d_in[5];
    const float* enc_w2   = (const float*)d_in[6];
    const float* enc_b2   = (const float*)d_in[7];
    const float* pool_w   = (const float*)d_in[8];
    const float* pool_b   = (const float*)d_in[9];
    const float* toz_w    = (const float*)d_in[10];
    const float* toz_b    = (const float*)d_in[11];
    const float* vp_w1    = (const float*)d_in[12];
    const float* vp_b1    = (const float*)d_in[13];
    const float* vp_w2    = (const float*)d_in[14];
    const float* vp_b2    = (const float*)d_in[15];
    const float* bridge_w = (const float*)d_in[16];
    const float* bridge_b = (const float*)d_in[17];

    float* out = (float*)d_out;
    float* out_recon  = out;                 // 1024*8*4 = 32768
    float* out_z      = out + 32768;         // 1024*2*4 =  8192
    float* out_s      = out + 40960;         // 262144*2 = 524288
    float* out_forces = out + 565248;        // 1024*2*2 =  4096
    float* out_V      = out + 569344;        // 1024

    pre_kernel<<<N_NODES / 256, 256>>>(x, pos);

    edge_kernel<<<N_EDGES / 256, 256>>>(ei, enc_w1, enc_b1, enc_w2, enc_b2);

    node_kernel<<<N_NODES / 256, 256>>>(batch, pool_w, pool_b, out_s);

    graph_kernel<<<NUM_GRAPHS, 32>>>(toz_w, toz_b, vp_w1, vp_b1, vp_w2, vp_b2,
                                     bridge_w, bridge_b,
                                     out_recon, out_z, out_forces, out_V);
}